// round 11
// baseline (speedup 1.0000x reference)
#include <cuda_runtime.h>
#include <cuda_fp16.h>
#include <cstdint>
#include <math.h>

#define T 2048
#define H 1024
#define E 8
#define NI 512          // I
#define SIH 2048        // SI
#define NPAIR (2*T)

#define SMEM_BYTES (3*32768)

// ---- fp16 operand buffers ----
__device__ __half g_xh [(size_t)T*H];
__device__ __half g_sgw[(size_t)SIH*H];
__device__ __half g_suw[(size_t)SIH*H];
__device__ __half g_sdw[(size_t)H*SIH];
__device__ __half g_gupw[(size_t)E*2*NI*H];
__device__ __half g_dnw[(size_t)E*H*NI];
__device__ __half g_s1h[(size_t)T*SIH];            // shared SwiGLU intermediate (fp16)
__device__ __half g_acth[(size_t)(NPAIR+128)*NI];  // expert SwiGLU intermediate (+pad rows)
// ---- fp16 GEMM outputs ----
__device__ __half g_shared2[(size_t)T*H];
__device__ __half g_pairout[(size_t)NPAIR*H];
// ---- routing state ----
__device__ int   g_top_e[T*2];
__device__ float g_top_w[T*2];
__device__ float g_gl[T];
__device__ int   g_count[E];
__device__ int   g_pair_token[NPAIR];
__device__ float g_pair_w[NPAIR];
__device__ int   g_pos[T*2];
__device__ int   g_offset[E];

// =============== PTX helpers ===============
__device__ __forceinline__ uint32_t smem_u32(const void* p) {
    uint32_t a;
    asm("{ .reg .u64 t; cvta.to.shared.u64 t, %1; cvt.u32.u64 %0, t; }" : "=r"(a) : "l"(p));
    return a;
}
__device__ __forceinline__ void cp16(uint32_t dst, const void* src) {
    asm volatile("cp.async.cg.shared.global [%0], [%1], 16;" :: "r"(dst), "l"(src) : "memory");
}
#define CP_COMMIT() asm volatile("cp.async.commit_group;" ::: "memory")
#define CP_WAIT1()  asm volatile("cp.async.wait_group 1;" ::: "memory")

__device__ __forceinline__ void ldsm_x4(uint32_t& r0, uint32_t& r1, uint32_t& r2, uint32_t& r3, uint32_t addr) {
    asm volatile("ldmatrix.sync.aligned.m8n8.x4.shared.b16 {%0,%1,%2,%3}, [%4];"
        : "=r"(r0), "=r"(r1), "=r"(r2), "=r"(r3) : "r"(addr));
}
__device__ __forceinline__ void mma16816(float* c, const uint32_t* a, uint32_t b0, uint32_t b1) {
    asm("mma.sync.aligned.m16n8k16.row.col.f32.f16.f16.f32 "
        "{%0,%1,%2,%3}, {%4,%5,%6,%7}, {%8,%9}, {%0,%1,%2,%3};\n"
        : "+f"(c[0]), "+f"(c[1]), "+f"(c[2]), "+f"(c[3])
        : "r"(a[0]), "r"(a[1]), "r"(a[2]), "r"(a[3]), "r"(b0), "r"(b1));
}

__device__ __forceinline__ float siluf(float g) { return g / (1.f + expf(-g)); }

// =============== GEMM core: 128(M) x NB(B-rows) x K, k-chunk 64, 3-stage cp.async, swizzled smem ===============
template<int DUAL, int NB>
__device__ __forceinline__ void gemm_body(
    const __half* __restrict__ A, const int* __restrict__ tokmap,
    const __half* __restrict__ Bg, const __half* __restrict__ Bu,
    __half* __restrict__ Cout, int ldo, const float* __restrict__ wrow,
    int K, int m0, int nb, int rowlim)
{
    constexpr int NJ   = NB / 32;
    constexpr int NBCH = NB / 32;
    constexpr uint32_t STG = 16384 + NB * 128;

    extern __shared__ __half dsm[];
    uint32_t sbase = smem_u32(dsm);
    int tid = threadIdx.x, warp = tid >> 5, lane = tid & 31;
    int wm = warp & 3, wn = warp >> 2;
    int g = lane >> 2, t4 = lane & 3;
    int lrow = lane & 15, hi = lane >> 4;

    float c[2][2*NJ][4] = {};

    const __half* aptr[4]; uint32_t adst[4];
    const __half* bptr[NBCH]; uint32_t bdst[NBCH];
    #pragma unroll
    for (int i = 0; i < 4; i++) {
        int id = i*256 + tid;
        int r = id >> 3, cq = id & 7;
        int gr = m0 + r;
        int srow;
        if (tokmap) srow = (gr < rowlim) ? tokmap[gr] : 0;
        else        srow = gr;
        aptr[i] = A + (size_t)srow * K + cq*8;
        adst[i] = (uint32_t)(r*128 + ((cq ^ (r & 7)) << 4));
    }
    #pragma unroll
    for (int i = 0; i < NBCH; i++) {
        int id = i*256 + tid;
        int r = id >> 3, cq = id & 7;
        const __half* brow;
        if (DUAL) {
            int h = r >> 6, s = r & 63;
            brow = (s < 32) ? (Bg + (size_t)(nb + h*32 + s) * K)
                            : (Bu + (size_t)(nb + h*32 + s - 32) * K);
        } else {
            brow = Bg + (size_t)(nb + r) * K;
        }
        bptr[i] = brow + cq*8;
        bdst[i] = (uint32_t)(r*128 + ((cq ^ (r & 7)) << 4));
    }

    int arow0 = wm*32 + lrow, arow1 = arow0 + 16;
    uint32_t abase0 = arow0*128, abase1 = arow1*128;
    uint32_t arx0 = (uint32_t)(arow0 & 7) << 4, arx1 = (uint32_t)(arow1 & 7) << 4;
    uint32_t bbase[NJ], brx[NJ];
    #pragma unroll
    for (int j = 0; j < NJ; j++) {
        int br = wn*(NB/2) + j*16 + lrow;
        bbase[j] = br*128;
        brx[j] = (uint32_t)(br & 7) << 4;
    }

    int NK = K / 64;
    #pragma unroll
    for (int s = 0; s < 2; s++) {
        uint32_t sA = sbase + s*STG, sB = sA + 16384;
        #pragma unroll
        for (int i = 0; i < 4; i++)    cp16(sA + adst[i], aptr[i] + s*64);
        #pragma unroll
        for (int i = 0; i < NBCH; i++) cp16(sB + bdst[i], bptr[i] + s*64);
        CP_COMMIT();
    }

    int stg = 0;
    for (int kt = 0; kt < NK; kt++) {
        CP_WAIT1();
        __syncthreads();
        if (kt + 2 < NK) {
            int s2 = stg + 2; if (s2 >= 3) s2 -= 3;
            uint32_t sA = sbase + s2*STG, sB = sA + 16384;
            int ko = (kt + 2) * 64;
            #pragma unroll
            for (int i = 0; i < 4; i++)    cp16(sA + adst[i], aptr[i] + ko);
            #pragma unroll
            for (int i = 0; i < NBCH; i++) cp16(sB + bdst[i], bptr[i] + ko);
        }
        CP_COMMIT();
        uint32_t sA = sbase + stg*STG, sB = sA + 16384;
        #pragma unroll
        for (int kk = 0; kk < 4; kk++) {
            uint32_t koff = (uint32_t)((kk*2 + hi) << 4);
            uint32_t a0[4], a1[4];
            ldsm_x4(a0[0], a0[1], a0[2], a0[3], sA + abase0 + (koff ^ arx0));
            ldsm_x4(a1[0], a1[1], a1[2], a1[3], sA + abase1 + (koff ^ arx1));
            #pragma unroll
            for (int j = 0; j < NJ; j++) {
                uint32_t r0, r1, r2, r3;
                ldsm_x4(r0, r1, r2, r3, sB + bbase[j] + (koff ^ brx[j]));
                mma16816(c[0][2*j],   a0, r0, r2);
                mma16816(c[0][2*j+1], a0, r1, r3);
                mma16816(c[1][2*j],   a1, r0, r2);
                mma16816(c[1][2*j+1], a1, r1, r3);
            }
        }
        if (++stg == 3) stg = 0;
    }

    #pragma unroll
    for (int im = 0; im < 2; im++) {
        int rowa = m0 + wm*32 + im*16 + g;
        int rowb = rowa + 8;
        if (DUAL) {
            float wa = 1.f, wb = 1.f;
            if (wrow) {
                if (rowa < rowlim) wa = wrow[rowa];
                if (rowb < rowlim) wb = wrow[rowb];
            }
            #pragma unroll
            for (int in = 0; in < 4; in++) {
                int col = nb + wn*32 + in*8 + t4*2;
                if (rowa < rowlim) {
                    float v0 = siluf(c[im][in][0]) * c[im][in+4][0] * wa;
                    float v1 = siluf(c[im][in][1]) * c[im][in+4][1] * wa;
                    *(__half2*)&Cout[(size_t)rowa*ldo + col] = __floats2half2_rn(v0, v1);
                }
                if (rowb < rowlim) {
                    float v0 = siluf(c[im][in][2]) * c[im][in+4][2] * wb;
                    float v1 = siluf(c[im][in][3]) * c[im][in+4][3] * wb;
                    *(__half2*)&Cout[(size_t)rowb*ldo + col] = __floats2half2_rn(v0, v1);
                }
            }
        } else {
            #pragma unroll
            for (int in = 0; in < 2*NJ; in++) {
                int col = nb + wn*(NB/2) + in*8 + t4*2;
                if (rowa < rowlim)
                    *(__half2*)&Cout[(size_t)rowa*ldo + col] = __floats2half2_rn(c[im][in][0], c[im][in][1]);
                if (rowb < rowlim)
                    *(__half2*)&Cout[(size_t)rowb*ldo + col] = __floats2half2_rn(c[im][in][2], c[im][in][3]);
            }
        }
    }
}

// =============== GEMM wrappers ===============
__global__ __launch_bounds__(256, 2) void gemm_s1_k() {
    gemm_body<1,128>(g_xh, nullptr, g_sgw, g_suw, g_s1h, SIH, nullptr,
                     H, blockIdx.y*128, blockIdx.x*64, T);
}
__global__ __launch_bounds__(256, 2) void gemm_s2_k() {
    gemm_body<0,64>(g_s1h, nullptr, g_sdw, nullptr, g_shared2, H, nullptr,
                    SIH, blockIdx.y*128, blockIdx.x*64, T);
}
__global__ __launch_bounds__(256, 2) void gemm_e1_k() {
    int e = blockIdx.z;
    int cnt = g_count[e], base = g_offset[e];
    int m0 = blockIdx.y * 128;
    if (m0 >= cnt) return;
    const __half* W = g_gupw + (size_t)e * 2 * NI * H;
    gemm_body<1,128>(g_xh, g_pair_token + base, W, W + (size_t)NI * H,
                     g_acth + (size_t)base * NI, NI, g_pair_w + base,
                     H, m0, blockIdx.x*64, cnt);
}
__global__ __launch_bounds__(256, 2) void gemm_e2_k() {
    int e = blockIdx.z;
    int cnt = g_count[e], base = g_offset[e];
    int m0 = blockIdx.y * 128;
    if (m0 >= cnt) return;
    gemm_body<0,128>(g_acth + (size_t)base * NI, nullptr, g_dnw + (size_t)e * H * NI, nullptr,
                     g_pairout + (size_t)base * H, H, nullptr,
                     NI, m0, blockIdx.x*128, cnt);
}

// =============== routing ===============
__global__ void reset8_kernel() { if (threadIdx.x < E) g_count[threadIdx.x] = 0; }

__global__ void router_kernel(const float* __restrict__ x,
                              const float* __restrict__ rw,
                              const float* __restrict__ seg) {
    int warp = (blockIdx.x * blockDim.x + threadIdx.x) >> 5;
    int lane = threadIdx.x & 31;
    if (warp >= T) return;
    const float* xr = x + (size_t)warp * H;
    float acc[E];
    #pragma unroll
    for (int e = 0; e < E; e++) acc[e] = 0.f;
    float accg = 0.f;
    for (int k = lane; k < H; k += 32) {
        float xv = xr[k];
        #pragma unroll
        for (int e = 0; e < E; e++) acc[e] += xv * rw[e*H + k];
        accg += xv * seg[k];
    }
    #pragma unroll
    for (int o = 16; o > 0; o >>= 1) {
        #pragma unroll
        for (int e = 0; e < E; e++) acc[e] += __shfl_xor_sync(0xffffffffu, acc[e], o);
        accg += __shfl_xor_sync(0xffffffffu, accg, o);
    }
    if (lane == 0) {
        int be = 0; float bv = acc[0];
        #pragma unroll
        for (int e = 1; e < E; e++) if (acc[e] > bv) { bv = acc[e]; be = e; }
        int se = -1; float sv = -1e30f;
        #pragma unroll
        for (int e = 0; e < E; e++) if (e != be && acc[e] > sv) { sv = acc[e]; se = e; }
        float w0 = 1.f / (1.f + expf(sv - bv));
        float w1 = 1.f - w0;
        g_top_e[warp*2+0] = be; g_top_e[warp*2+1] = se;
        g_top_w[warp*2+0] = w0; g_top_w[warp*2+1] = w1;
        g_gl[warp] = accg;
        atomicAdd(&g_count[be], 1);
        atomicAdd(&g_count[se], 1);
    }
}

__global__ void scan_scatter_kernel() {
    __shared__ int s_fill[E];
    int tid = threadIdx.x;
    if (tid == 0) {
        int off = 0;
        for (int e = 0; e < E; e++) {
            g_offset[e] = off;
            s_fill[e] = off;
            off += g_count[e];
        }
    }
    __syncthreads();
    for (int t = tid; t < T; t += blockDim.x) {
        #pragma unroll
        for (int k = 0; k < 2; k++) {
            int e = g_top_e[t*2+k];
            int slot = atomicAdd(&s_fill[e], 1);
            g_pair_token[slot] = t;
            g_pair_w[slot] = g_top_w[t*2+k];
            g_pos[t*2+k] = slot;
        }
    }
}

// =============== fp32->fp16 conversion, split early/late ===============
__device__ __forceinline__ void cvt8(const float* __restrict__ src, __half* __restrict__ dst, size_t i) {
    float4 a = *(const float4*)(src + i);
    float4 b = *(const float4*)(src + i + 4);
    __half h[8];
    h[0]=__float2half_rn(a.x); h[1]=__float2half_rn(a.y); h[2]=__float2half_rn(a.z); h[3]=__float2half_rn(a.w);
    h[4]=__float2half_rn(b.x); h[5]=__float2half_rn(b.y); h[6]=__float2half_rn(b.z); h[7]=__float2half_rn(b.w);
    *(uint4*)(dst + i) = *(uint4*)h;
}
#define SZ_X   ((size_t)T*H)
#define SZ_SGW ((size_t)SIH*H)
#define SZ_SUW ((size_t)SIH*H)
#define SZ_SDW ((size_t)H*SIH)
#define SZ_GUP ((size_t)E*2*NI*H)
#define SZ_DN  ((size_t)E*H*NI)
// early: x, sgw, suw, gup  (phase-1 operands)
#define E0 (SZ_X)
#define E1 (E0+SZ_SGW)
#define E2 (E1+SZ_SUW)
#define E3 (E2+SZ_GUP)
// late: sdw, dn  (phase-2 operands)
#define L0 (SZ_SDW)
#define L1 (L0+SZ_DN)
__device__ __forceinline__ void cvt8_early(size_t i,
    const float* x, const float* sgw, const float* suw, const float* gup) {
    if      (i < E0) cvt8(x,   g_xh,   i);
    else if (i < E1) cvt8(sgw, g_sgw,  i - E0);
    else if (i < E2) cvt8(suw, g_suw,  i - E1);
    else if (i < E3) cvt8(gup, g_gupw, i - E2);
}
__global__ void cvt_early_k(const float* __restrict__ x,   const float* __restrict__ sgw,
                            const float* __restrict__ suw, const float* __restrict__ gup) {
    size_t i = ((size_t)blockIdx.x * blockDim.x + threadIdx.x) * 16;
    cvt8_early(i, x, sgw, suw, gup);
    cvt8_early(i + 8, x, sgw, suw, gup);
}
__device__ __forceinline__ void cvt8_late(size_t i, const float* sdw, const float* dn) {
    if      (i < L0) cvt8(sdw, g_sdw, i);
    else if (i < L1) cvt8(dn,  g_dnw, i - L0);
}
__global__ void cvt_late_k(const float* __restrict__ sdw, const float* __restrict__ dn) {
    size_t i = ((size_t)blockIdx.x * blockDim.x + threadIdx.x) * 16;
    cvt8_late(i, sdw, dn);
    cvt8_late(i + 8, sdw, dn);
}

// =============== combine ===============
__global__ void combine_kernel(float* __restrict__ out) {
    int idx = blockIdx.x * blockDim.x + threadIdx.x;
    if (idx >= T*H/4) return;
    int t  = idx / (H/4);
    int c4 = (idx % (H/4)) * 4;
    int p0 = g_pos[t*2+0], p1 = g_pos[t*2+1];
    float sgate = 1.f / (1.f + expf(-g_gl[t]));
    __half2 a0 = *(__half2*)&g_pairout[(size_t)p0*H + c4];
    __half2 a1 = *(__half2*)&g_pairout[(size_t)p0*H + c4 + 2];
    __half2 b0 = *(__half2*)&g_pairout[(size_t)p1*H + c4];
    __half2 b1 = *(__half2*)&g_pairout[(size_t)p1*H + c4 + 2];
    __half2 s0 = *(__half2*)&g_shared2[(size_t)t*H + c4];
    __half2 s1 = *(__half2*)&g_shared2[(size_t)t*H + c4 + 2];
    float2 af0 = __half22float2(a0), af1 = __half22float2(a1);
    float2 bf0 = __half22float2(b0), bf1 = __half22float2(b1);
    float2 sf0 = __half22float2(s0), sf1 = __half22float2(s1);
    float4 o;
    o.x = af0.x + bf0.x + sgate * sf0.x;
    o.y = af0.y + bf0.y + sgate * sf0.y;
    o.z = af1.x + bf1.x + sgate * sf1.x;
    o.w = af1.y + bf1.y + sgate * sf1.y;
    *(float4*)&out[(size_t)t*H + c4] = o;
}

extern "C" void kernel_launch(void* const* d_in, const int* in_sizes, int n_in,
                              void* d_out, int out_size) {
    const float* x    = (const float*)d_in[0];
    const float* rw   = (const float*)d_in[1];
    const float* gup  = (const float*)d_in[2];
    const float* down = (const float*)d_in[3];
    const float* sgw  = (const float*)d_in[4];
    const float* suw  = (const float*)d_in[5];
    const float* sdw  = (const float*)d_in[6];
    const float* seg  = (const float*)d_in[7];
    float* out = (float*)d_out;

    static cudaStream_t st1 = nullptr, st2 = nullptr, st3 = nullptr;
    static cudaEvent_t ev0 = nullptr, evA = nullptr, evR = nullptr, evB = nullptr, evL = nullptr;
    static bool init_done = false;
    if (!init_done) {
        cudaFuncSetAttribute(gemm_s1_k, cudaFuncAttributeMaxDynamicSharedMemorySize, SMEM_BYTES);
        cudaFuncSetAttribute(gemm_s2_k, cudaFuncAttributeMaxDynamicSharedMemorySize, SMEM_BYTES);
        cudaFuncSetAttribute(gemm_e1_k, cudaFuncAttributeMaxDynamicSharedMemorySize, SMEM_BYTES);
        cudaFuncSetAttribute(gemm_e2_k, cudaFuncAttributeMaxDynamicSharedMemorySize, SMEM_BYTES);
        cudaStreamCreateWithFlags(&st1, cudaStreamNonBlocking);
        cudaStreamCreateWithFlags(&st2, cudaStreamNonBlocking);
        cudaStreamCreateWithFlags(&st3, cudaStreamNonBlocking);
        cudaEventCreateWithFlags(&ev0, cudaEventDisableTiming);
        cudaEventCreateWithFlags(&evA, cudaEventDisableTiming);
        cudaEventCreateWithFlags(&evR, cudaEventDisableTiming);
        cudaEventCreateWithFlags(&evB, cudaEventDisableTiming);
        cudaEventCreateWithFlags(&evL, cudaEventDisableTiming);
        init_done = true;
    }

    // fork: bring side streams into the graph
    cudaEventRecord(ev0, 0);
    cudaStreamWaitEvent(st1, ev0, 0);
    cudaStreamWaitEvent(st2, ev0, 0);
    cudaStreamWaitEvent(st3, ev0, 0);

    // st1: routing chain (fp32 inputs only; overlaps cvt_early)
    reset8_kernel<<<1, 32, 0, st1>>>();
    router_kernel<<<T/8, 256, 0, st1>>>(x, rw, seg);
    scan_scatter_kernel<<<1, 1024, 0, st1>>>();
    cudaEventRecord(evR, st1);

    // main: phase-1 operand conversion (critical prefix)
    cvt_early_k<<<(unsigned)((E3/16 + 255)/256), 256>>>(x, sgw, suw, gup);
    cudaEventRecord(evA, 0);

    // st3: phase-2 operand conversion — after cvt_early, overlapped with phase-1 GEMMs
    cudaStreamWaitEvent(st3, evA, 0);
    cvt_late_k<<<(unsigned)((L1/16 + 255)/256), 256, 0, st3>>>(sdw, down);
    cudaEventRecord(evL, st3);

    // st2: shared-expert chain
    cudaStreamWaitEvent(st2, evA, 0);
    gemm_s1_k<<<dim3(SIH/64, T/128), 256, SMEM_BYTES, st2>>>();
    cudaStreamWaitEvent(st2, evL, 0);
    gemm_s2_k<<<dim3(H/64, T/128), 256, 3*(16384 + 64*128), st2>>>();
    cudaEventRecord(evB, st2);

    // main: expert chain (cvt_early stream-ordered; routing via evR; dnw via evL)
    cudaStreamWaitEvent(0, evR, 0);
    gemm_e1_k<<<dim3(NI/64, NPAIR/128, E), 256, SMEM_BYTES>>>();
    cudaStreamWaitEvent(0, evL, 0);
    gemm_e2_k<<<dim3(H/128, NPAIR/128, E), 256, SMEM_BYTES>>>();

    // join
    cudaStreamWaitEvent(0, evB, 0);
    combine_kernel<<<(T*H/4 + 255)/256, 256>>>(out);
}

// round 12
// speedup vs baseline: 1.0536x; 1.0536x over previous
#include <cuda_runtime.h>
#include <cuda_fp16.h>
#include <cstdint>
#include <math.h>

#define T 2048
#define H 1024
#define E 8
#define NI 512          // I
#define SIH 2048        // SI
#define NPAIR (2*T)

// ---- fp16 operand buffers ----
__device__ __half g_xh [(size_t)T*H];
__device__ __half g_sgw[(size_t)SIH*H];
__device__ __half g_suw[(size_t)SIH*H];
__device__ __half g_sdw[(size_t)H*SIH];
__device__ __half g_gupw[(size_t)E*2*NI*H];
__device__ __half g_dnw[(size_t)E*H*NI];
__device__ __half g_s1h[(size_t)T*SIH];            // shared SwiGLU intermediate (fp16)
__device__ __half g_acth[(size_t)(NPAIR+128)*NI];  // expert SwiGLU intermediate (+pad rows)
// ---- fp16 GEMM outputs ----
__device__ __half g_shared2[(size_t)T*H];
__device__ __half g_pairout[(size_t)NPAIR*H];
// ---- routing state ----
__device__ int   g_top_e[T*2];
__device__ float g_top_w[T*2];
__device__ float g_gl[T];
__device__ int   g_count[E];
__device__ int   g_pair_token[NPAIR];
__device__ float g_pair_w[NPAIR];
__device__ int   g_pos[T*2];
__device__ int   g_offset[E];

// =============== PTX helpers ===============
__device__ __forceinline__ uint32_t smem_u32(const void* p) {
    uint32_t a;
    asm("{ .reg .u64 t; cvta.to.shared.u64 t, %1; cvt.u32.u64 %0, t; }" : "=r"(a) : "l"(p));
    return a;
}
__device__ __forceinline__ void cp16(uint32_t dst, const void* src) {
    asm volatile("cp.async.cg.shared.global [%0], [%1], 16;" :: "r"(dst), "l"(src) : "memory");
}
#define CP_COMMIT() asm volatile("cp.async.commit_group;" ::: "memory")
#define CP_WAIT1()  asm volatile("cp.async.wait_group 1;" ::: "memory")
#define CP_WAIT0()  asm volatile("cp.async.wait_group 0;" ::: "memory")

__device__ __forceinline__ void ldsm_x4(uint32_t& r0, uint32_t& r1, uint32_t& r2, uint32_t& r3, uint32_t addr) {
    asm volatile("ldmatrix.sync.aligned.m8n8.x4.shared.b16 {%0,%1,%2,%3}, [%4];"
        : "=r"(r0), "=r"(r1), "=r"(r2), "=r"(r3) : "r"(addr));
}
__device__ __forceinline__ void mma16816(float* c, const uint32_t* a, uint32_t b0, uint32_t b1) {
    asm("mma.sync.aligned.m16n8k16.row.col.f32.f16.f16.f32 "
        "{%0,%1,%2,%3}, {%4,%5,%6,%7}, {%8,%9}, {%0,%1,%2,%3};\n"
        : "+f"(c[0]), "+f"(c[1]), "+f"(c[2]), "+f"(c[3])
        : "r"(a[0]), "r"(a[1]), "r"(a[2]), "r"(a[3]), "r"(b0), "r"(b1));
}

__device__ __forceinline__ float siluf(float g) { return g / (1.f + expf(-g)); }

// =============== GEMM core: 64(M) x NB(B-rows) x K, k-chunk 64, 2-stage cp.async, 128 threads ===============
// 4 warps: wm = warp&1 (2 along M, 32 rows each), wn = warp>>1 (2 along B-rows, NB/2 each).
// Stage: A tile 64x64h (8KB) at +0, B tile NBx64h at +8KB. Stage stride = 8KB + NB*128.
// Row = 128B; 16B chunk cq stored at cq ^ (row&7).
// DUAL=0: C[M,NB] fp16.  DUAL=1 (NB=128): C[M,64] fp16 = silu(G)*U*w; B rows interleave gate/up.
template<int DUAL, int NB>
__device__ __forceinline__ void gemm_body(
    const __half* __restrict__ A, const int* __restrict__ tokmap,
    const __half* __restrict__ Bg, const __half* __restrict__ Bu,
    __half* __restrict__ Cout, int ldo, const float* __restrict__ wrow,
    int K, int m0, int nb, int rowlim)
{
    constexpr int NJ   = NB / 32;              // B fragments (16 rows) per warp
    constexpr int NBCH = NB / 16;              // B cp16 chunks per thread per stage
    constexpr uint32_t STG = 8192 + NB * 128;

    extern __shared__ __half dsm[];
    uint32_t sbase = smem_u32(dsm);
    int tid = threadIdx.x, warp = tid >> 5, lane = tid & 31;
    int wm = warp & 1, wn = warp >> 1;
    int g = lane >> 2, t4 = lane & 3;
    int lrow = lane & 15, hi = lane >> 4;

    float c[2][2*NJ][4] = {};

    // ---- cp.async loaders: A 512 chunks (4/thr), B NB*8 chunks (NBCH/thr) ----
    const __half* aptr[4]; uint32_t adst[4];
    const __half* bptr[NBCH]; uint32_t bdst[NBCH];
    #pragma unroll
    for (int i = 0; i < 4; i++) {
        int id = i*128 + tid;
        int r = id >> 3, cq = id & 7;          // row 0..63
        int gr = m0 + r;
        int srow;
        if (tokmap) srow = (gr < rowlim) ? tokmap[gr] : 0;
        else        srow = gr;                 // buffers padded so OOB rows readable
        aptr[i] = A + (size_t)srow * K + cq*8;
        adst[i] = (uint32_t)(r*128 + ((cq ^ (r & 7)) << 4));
    }
    #pragma unroll
    for (int i = 0; i < NBCH; i++) {
        int id = i*128 + tid;
        int r = id >> 3, cq = id & 7;          // row 0..NB-1
        const __half* brow;
        if (DUAL) {
            int h = r >> 6, s = r & 63;
            brow = (s < 32) ? (Bg + (size_t)(nb + h*32 + s) * K)
                            : (Bu + (size_t)(nb + h*32 + s - 32) * K);
        } else {
            brow = Bg + (size_t)(nb + r) * K;
        }
        bptr[i] = brow + cq*8;
        bdst[i] = (uint32_t)(r*128 + ((cq ^ (r & 7)) << 4));
    }

    // ---- ldmatrix address components ----
    int arow0 = wm*32 + lrow, arow1 = arow0 + 16;
    uint32_t abase0 = arow0*128, abase1 = arow1*128;
    uint32_t arx0 = (uint32_t)(arow0 & 7) << 4, arx1 = (uint32_t)(arow1 & 7) << 4;
    uint32_t bbase[NJ], brx[NJ];
    #pragma unroll
    for (int j = 0; j < NJ; j++) {
        int br = wn*(NB/2) + j*16 + lrow;
        bbase[j] = br*128;
        brx[j] = (uint32_t)(br & 7) << 4;
    }

    int NK = K / 64;
    // ---- prologue: stage 0 ----
    {
        uint32_t sA = sbase, sB = sA + 8192;
        #pragma unroll
        for (int i = 0; i < 4; i++)    cp16(sA + adst[i], aptr[i]);
        #pragma unroll
        for (int i = 0; i < NBCH; i++) cp16(sB + bdst[i], bptr[i]);
        CP_COMMIT();
    }

    for (int kt = 0; kt < NK; kt++) {
        if (kt + 1 < NK) {
            uint32_t sA = sbase + ((kt+1) & 1)*STG, sB = sA + 8192;
            int ko = (kt + 1) * 64;
            #pragma unroll
            for (int i = 0; i < 4; i++)    cp16(sA + adst[i], aptr[i] + ko);
            #pragma unroll
            for (int i = 0; i < NBCH; i++) cp16(sB + bdst[i], bptr[i] + ko);
            CP_COMMIT();
            CP_WAIT1();
        } else {
            CP_WAIT0();
        }
        __syncthreads();
        uint32_t sA = sbase + (kt & 1)*STG, sB = sA + 8192;
        #pragma unroll
        for (int kk = 0; kk < 4; kk++) {
            uint32_t koff = (uint32_t)((kk*2 + hi) << 4);
            uint32_t a0[4], a1[4];
            ldsm_x4(a0[0], a0[1], a0[2], a0[3], sA + abase0 + (koff ^ arx0));
            ldsm_x4(a1[0], a1[1], a1[2], a1[3], sA + abase1 + (koff ^ arx1));
            #pragma unroll
            for (int j = 0; j < NJ; j++) {
                uint32_t r0, r1, r2, r3;
                ldsm_x4(r0, r1, r2, r3, sB + bbase[j] + (koff ^ brx[j]));
                mma16816(c[0][2*j],   a0, r0, r2);
                mma16816(c[0][2*j+1], a0, r1, r3);
                mma16816(c[1][2*j],   a1, r0, r2);
                mma16816(c[1][2*j+1], a1, r1, r3);
            }
        }
        __syncthreads();   // all warps done with buf kt&1 before next iteration overwrites it
    }

    // ---- epilogue (fp16 outputs in both modes) ----
    #pragma unroll
    for (int im = 0; im < 2; im++) {
        int rowa = m0 + wm*32 + im*16 + g;
        int rowb = rowa + 8;
        if (DUAL) {
            float wa = 1.f, wb = 1.f;
            if (wrow) {
                if (rowa < rowlim) wa = wrow[rowa];
                if (rowb < rowlim) wb = wrow[rowb];
            }
            #pragma unroll
            for (int in = 0; in < 4; in++) {
                int col = nb + wn*32 + in*8 + t4*2;
                if (rowa < rowlim) {
                    float v0 = siluf(c[im][in][0]) * c[im][in+4][0] * wa;
                    float v1 = siluf(c[im][in][1]) * c[im][in+4][1] * wa;
                    *(__half2*)&Cout[(size_t)rowa*ldo + col] = __floats2half2_rn(v0, v1);
                }
                if (rowb < rowlim) {
                    float v0 = siluf(c[im][in][2]) * c[im][in+4][2] * wb;
                    float v1 = siluf(c[im][in][3]) * c[im][in+4][3] * wb;
                    *(__half2*)&Cout[(size_t)rowb*ldo + col] = __floats2half2_rn(v0, v1);
                }
            }
        } else {
            #pragma unroll
            for (int in = 0; in < 2*NJ; in++) {
                int col = nb + wn*(NB/2) + in*8 + t4*2;
                if (rowa < rowlim)
                    *(__half2*)&Cout[(size_t)rowa*ldo + col] = __floats2half2_rn(c[im][in][0], c[im][in][1]);
                if (rowb < rowlim)
                    *(__half2*)&Cout[(size_t)rowb*ldo + col] = __floats2half2_rn(c[im][in][2], c[im][in][3]);
            }
        }
    }
}

#define SMEM_128 (2*(8192 + 128*128))   // 49152
#define SMEM_64  (2*(8192 + 64*128))    // 32768

// =============== GEMM wrappers ===============
__global__ __launch_bounds__(128, 4) void gemm_s1_k() {
    gemm_body<1,128>(g_xh, nullptr, g_sgw, g_suw, g_s1h, SIH, nullptr,
                     H, blockIdx.y*64, blockIdx.x*64, T);
}
__global__ __launch_bounds__(128, 4) void gemm_s2_k() {
    gemm_body<0,64>(g_s1h, nullptr, g_sdw, nullptr, g_shared2, H, nullptr,
                    SIH, blockIdx.y*64, blockIdx.x*64, T);
}
__global__ __launch_bounds__(128, 4) void gemm_e1_k() {
    int e = blockIdx.z;
    int cnt = g_count[e], base = g_offset[e];
    int m0 = blockIdx.y * 64;
    if (m0 >= cnt) return;
    const __half* W = g_gupw + (size_t)e * 2 * NI * H;
    gemm_body<1,128>(g_xh, g_pair_token + base, W, W + (size_t)NI * H,
                     g_acth + (size_t)base * NI, NI, g_pair_w + base,
                     H, m0, blockIdx.x*64, cnt);
}
__global__ __launch_bounds__(128, 4) void gemm_e2_k() {
    int e = blockIdx.z;
    int cnt = g_count[e], base = g_offset[e];
    int m0 = blockIdx.y * 64;
    if (m0 >= cnt) return;
    gemm_body<0,128>(g_acth + (size_t)base * NI, nullptr, g_dnw + (size_t)e * H * NI, nullptr,
                     g_pairout + (size_t)base * H, H, nullptr,
                     NI, m0, blockIdx.x*128, cnt);
}

// =============== routing ===============
__global__ void reset8_kernel() { if (threadIdx.x < E) g_count[threadIdx.x] = 0; }

__global__ void router_kernel(const float* __restrict__ x,
                              const float* __restrict__ rw,
                              const float* __restrict__ seg) {
    int warp = (blockIdx.x * blockDim.x + threadIdx.x) >> 5;
    int lane = threadIdx.x & 31;
    if (warp >= T) return;
    const float* xr = x + (size_t)warp * H;
    float acc[E];
    #pragma unroll
    for (int e = 0; e < E; e++) acc[e] = 0.f;
    float accg = 0.f;
    for (int k = lane; k < H; k += 32) {
        float xv = xr[k];
        #pragma unroll
        for (int e = 0; e < E; e++) acc[e] += xv * rw[e*H + k];
        accg += xv * seg[k];
    }
    #pragma unroll
    for (int o = 16; o > 0; o >>= 1) {
        #pragma unroll
        for (int e = 0; e < E; e++) acc[e] += __shfl_xor_sync(0xffffffffu, acc[e], o);
        accg += __shfl_xor_sync(0xffffffffu, accg, o);
    }
    if (lane == 0) {
        int be = 0; float bv = acc[0];
        #pragma unroll
        for (int e = 1; e < E; e++) if (acc[e] > bv) { bv = acc[e]; be = e; }
        int se = -1; float sv = -1e30f;
        #pragma unroll
        for (int e = 0; e < E; e++) if (e != be && acc[e] > sv) { sv = acc[e]; se = e; }
        float w0 = 1.f / (1.f + expf(sv - bv));
        float w1 = 1.f - w0;
        g_top_e[warp*2+0] = be; g_top_e[warp*2+1] = se;
        g_top_w[warp*2+0] = w0; g_top_w[warp*2+1] = w1;
        g_gl[warp] = accg;
        atomicAdd(&g_count[be], 1);
        atomicAdd(&g_count[se], 1);
    }
}

__global__ void scan_scatter_kernel() {
    __shared__ int s_fill[E];
    int tid = threadIdx.x;
    if (tid == 0) {
        int off = 0;
        for (int e = 0; e < E; e++) {
            g_offset[e] = off;
            s_fill[e] = off;
            off += g_count[e];
        }
    }
    __syncthreads();
    for (int t = tid; t < T; t += blockDim.x) {
        #pragma unroll
        for (int k = 0; k < 2; k++) {
            int e = g_top_e[t*2+k];
            int slot = atomicAdd(&s_fill[e], 1);
            g_pair_token[slot] = t;
            g_pair_w[slot] = g_top_w[t*2+k];
            g_pos[t*2+k] = slot;
        }
    }
}

// =============== fp32->fp16 conversion, split early/late ===============
__device__ __forceinline__ void cvt8(const float* __restrict__ src, __half* __restrict__ dst, size_t i) {
    float4 a = *(const float4*)(src + i);
    float4 b = *(const float4*)(src + i + 4);
    __half h[8];
    h[0]=__float2half_rn(a.x); h[1]=__float2half_rn(a.y); h[2]=__float2half_rn(a.z); h[3]=__float2half_rn(a.w);
    h[4]=__float2half_rn(b.x); h[5]=__float2half_rn(b.y); h[6]=__float2half_rn(b.z); h[7]=__float2half_rn(b.w);
    *(uint4*)(dst + i) = *(uint4*)h;
}
#define SZ_X   ((size_t)T*H)
#define SZ_SGW ((size_t)SIH*H)
#define SZ_SUW ((size_t)SIH*H)
#define SZ_SDW ((size_t)H*SIH)
#define SZ_GUP ((size_t)E*2*NI*H)
#define SZ_DN  ((size_t)E*H*NI)
#define E0 (SZ_X)
#define E1 (E0+SZ_SGW)
#define E2 (E1+SZ_SUW)
#define E3 (E2+SZ_GUP)
#define L0 (SZ_SDW)
#define L1 (L0+SZ_DN)
__device__ __forceinline__ void cvt8_early(size_t i,
    const float* x, const float* sgw, const float* suw, const float* gup) {
    if      (i < E0) cvt8(x,   g_xh,   i);
    else if (i < E1) cvt8(sgw, g_sgw,  i - E0);
    else if (i < E2) cvt8(suw, g_suw,  i - E1);
    else if (i < E3) cvt8(gup, g_gupw, i - E2);
}
__global__ void cvt_early_k(const float* __restrict__ x,   const float* __restrict__ sgw,
                            const float* __restrict__ suw, const float* __restrict__ gup) {
    size_t i = ((size_t)blockIdx.x * blockDim.x + threadIdx.x) * 16;
    cvt8_early(i, x, sgw, suw, gup);
    cvt8_early(i + 8, x, sgw, suw, gup);
}
__device__ __forceinline__ void cvt8_late(size_t i, const float* sdw, const float* dn) {
    if      (i < L0) cvt8(sdw, g_sdw, i);
    else if (i < L1) cvt8(dn,  g_dnw, i - L0);
}
__global__ void cvt_late_k(const float* __restrict__ sdw, const float* __restrict__ dn) {
    size_t i = ((size_t)blockIdx.x * blockDim.x + threadIdx.x) * 16;
    cvt8_late(i, sdw, dn);
    cvt8_late(i + 8, sdw, dn);
}

// =============== combine ===============
__global__ void combine_kernel(float* __restrict__ out) {
    int idx = blockIdx.x * blockDim.x + threadIdx.x;
    if (idx >= T*H/4) return;
    int t  = idx / (H/4);
    int c4 = (idx % (H/4)) * 4;
    int p0 = g_pos[t*2+0], p1 = g_pos[t*2+1];
    float sgate = 1.f / (1.f + expf(-g_gl[t]));
    __half2 a0 = *(__half2*)&g_pairout[(size_t)p0*H + c4];
    __half2 a1 = *(__half2*)&g_pairout[(size_t)p0*H + c4 + 2];
    __half2 b0 = *(__half2*)&g_pairout[(size_t)p1*H + c4];
    __half2 b1 = *(__half2*)&g_pairout[(size_t)p1*H + c4 + 2];
    __half2 s0 = *(__half2*)&g_shared2[(size_t)t*H + c4];
    __half2 s1 = *(__half2*)&g_shared2[(size_t)t*H + c4 + 2];
    float2 af0 = __half22float2(a0), af1 = __half22float2(a1);
    float2 bf0 = __half22float2(b0), bf1 = __half22float2(b1);
    float2 sf0 = __half22float2(s0), sf1 = __half22float2(s1);
    float4 o;
    o.x = af0.x + bf0.x + sgate * sf0.x;
    o.y = af0.y + bf0.y + sgate * sf0.y;
    o.z = af1.x + bf1.x + sgate * sf1.x;
    o.w = af1.y + bf1.y + sgate * sf1.y;
    *(float4*)&out[(size_t)t*H + c4] = o;
}

extern "C" void kernel_launch(void* const* d_in, const int* in_sizes, int n_in,
                              void* d_out, int out_size) {
    const float* x    = (const float*)d_in[0];
    const float* rw   = (const float*)d_in[1];
    const float* gup  = (const float*)d_in[2];
    const float* down = (const float*)d_in[3];
    const float* sgw  = (const float*)d_in[4];
    const float* suw  = (const float*)d_in[5];
    const float* sdw  = (const float*)d_in[6];
    const float* seg  = (const float*)d_in[7];
    float* out = (float*)d_out;

    static cudaStream_t st1 = nullptr, st2 = nullptr, st3 = nullptr;
    static cudaEvent_t ev0 = nullptr, evA = nullptr, evR = nullptr, evB = nullptr, evL = nullptr;
    static bool init_done = false;
    if (!init_done) {
        cudaFuncSetAttribute(gemm_s1_k, cudaFuncAttributeMaxDynamicSharedMemorySize, SMEM_128);
        cudaFuncSetAttribute(gemm_s2_k, cudaFuncAttributeMaxDynamicSharedMemorySize, SMEM_64);
        cudaFuncSetAttribute(gemm_e1_k, cudaFuncAttributeMaxDynamicSharedMemorySize, SMEM_128);
        cudaFuncSetAttribute(gemm_e2_k, cudaFuncAttributeMaxDynamicSharedMemorySize, SMEM_128);
        cudaStreamCreateWithFlags(&st1, cudaStreamNonBlocking);
        cudaStreamCreateWithFlags(&st2, cudaStreamNonBlocking);
        cudaStreamCreateWithFlags(&st3, cudaStreamNonBlocking);
        cudaEventCreateWithFlags(&ev0, cudaEventDisableTiming);
        cudaEventCreateWithFlags(&evA, cudaEventDisableTiming);
        cudaEventCreateWithFlags(&evR, cudaEventDisableTiming);
        cudaEventCreateWithFlags(&evB, cudaEventDisableTiming);
        cudaEventCreateWithFlags(&evL, cudaEventDisableTiming);
        init_done = true;
    }

    // fork
    cudaEventRecord(ev0, 0);
    cudaStreamWaitEvent(st1, ev0, 0);
    cudaStreamWaitEvent(st2, ev0, 0);
    cudaStreamWaitEvent(st3, ev0, 0);

    // st1: routing chain (overlaps cvt_early)
    reset8_kernel<<<1, 32, 0, st1>>>();
    router_kernel<<<T/8, 256, 0, st1>>>(x, rw, seg);
    scan_scatter_kernel<<<1, 1024, 0, st1>>>();
    cudaEventRecord(evR, st1);

    // main: phase-1 operand conversion
    cvt_early_k<<<(unsigned)((E3/16 + 255)/256), 256>>>(x, sgw, suw, gup);
    cudaEventRecord(evA, 0);

    // st3: phase-2 operand conversion overlapped with phase-1 GEMMs
    cudaStreamWaitEvent(st3, evA, 0);
    cvt_late_k<<<(unsigned)((L1/16 + 255)/256), 256, 0, st3>>>(sdw, down);
    cudaEventRecord(evL, st3);

    // st2: shared-expert chain
    cudaStreamWaitEvent(st2, evA, 0);
    gemm_s1_k<<<dim3(SIH/64, T/64), 128, SMEM_128, st2>>>();
    cudaStreamWaitEvent(st2, evL, 0);
    gemm_s2_k<<<dim3(H/64, T/64), 128, SMEM_64, st2>>>();
    cudaEventRecord(evB, st2);

    // main: expert chain
    cudaStreamWaitEvent(0, evR, 0);
    gemm_e1_k<<<dim3(NI/64, NPAIR/64, E), 128, SMEM_128>>>();
    cudaStreamWaitEvent(0, evL, 0);
    gemm_e2_k<<<dim3(H/128, NPAIR/64, E), 128, SMEM_128>>>();

    // join
    cudaStreamWaitEvent(0, evB, 0);
    combine_kernel<<<(T*H/4 + 255)/256, 256>>>(out);
}

// round 13
// speedup vs baseline: 1.0543x; 1.0006x over previous
#include <cuda_runtime.h>
#include <cuda_fp16.h>
#include <cstdint>
#include <math.h>

#define T 2048
#define H 1024
#define E 8
#define NI 512          // I
#define SIH 2048        // SI
#define NPAIR (2*T)

// ---- fp16 operand buffers ----
__device__ __half g_xh [(size_t)T*H];
__device__ __half g_sgw[(size_t)SIH*H];
__device__ __half g_suw[(size_t)SIH*H];
__device__ __half g_sdw[(size_t)H*SIH];
__device__ __half g_gupw[(size_t)E*2*NI*H];
__device__ __half g_dnw[(size_t)E*H*NI];
__device__ __half g_s1h[(size_t)T*SIH];            // shared SwiGLU intermediate (fp16)
__device__ __half g_acth[(size_t)(NPAIR+128)*NI];  // expert SwiGLU intermediate (+pad rows)
// ---- fp16 GEMM outputs ----
__device__ __half g_shared2[(size_t)T*H];
__device__ __half g_pairout[(size_t)NPAIR*H];
// ---- routing state ----
__device__ int   g_top_e[T*2];
__device__ float g_top_w[T*2];
__device__ float g_gl[T];
__device__ int   g_count[E];
__device__ int   g_pair_token[NPAIR];
__device__ float g_pair_w[NPAIR];
__device__ int   g_pos[T*2];
__device__ int   g_offset[E];

// =============== PTX helpers ===============
__device__ __forceinline__ uint32_t smem_u32(const void* p) {
    uint32_t a;
    asm("{ .reg .u64 t; cvta.to.shared.u64 t, %1; cvt.u32.u64 %0, t; }" : "=r"(a) : "l"(p));
    return a;
}
__device__ __forceinline__ void cp16(uint32_t dst, const void* src) {
    asm volatile("cp.async.cg.shared.global [%0], [%1], 16;" :: "r"(dst), "l"(src) : "memory");
}
#define CP_COMMIT() asm volatile("cp.async.commit_group;" ::: "memory")
#define CP_WAIT1()  asm volatile("cp.async.wait_group 1;" ::: "memory")
#define CP_WAIT0()  asm volatile("cp.async.wait_group 0;" ::: "memory")

__device__ __forceinline__ void ldsm_x4(uint32_t& r0, uint32_t& r1, uint32_t& r2, uint32_t& r3, uint32_t addr) {
    asm volatile("ldmatrix.sync.aligned.m8n8.x4.shared.b16 {%0,%1,%2,%3}, [%4];"
        : "=r"(r0), "=r"(r1), "=r"(r2), "=r"(r3) : "r"(addr));
}
__device__ __forceinline__ void mma16816(float* c, const uint32_t* a, uint32_t b0, uint32_t b1) {
    asm("mma.sync.aligned.m16n8k16.row.col.f32.f16.f16.f32 "
        "{%0,%1,%2,%3}, {%4,%5,%6,%7}, {%8,%9}, {%0,%1,%2,%3};\n"
        : "+f"(c[0]), "+f"(c[1]), "+f"(c[2]), "+f"(c[3])
        : "r"(a[0]), "r"(a[1]), "r"(a[2]), "r"(a[3]), "r"(b0), "r"(b1));
}

__device__ __forceinline__ float siluf(float g) { return g / (1.f + expf(-g)); }

// =============== GEMM core: 64(M) x NB(B-rows) x K, k-chunk 64, 2-stage cp.async, 128 threads ===============
// 4 warps: wm = warp&1 (2 along M, 32 rows each), wn = warp>>1 (2 along B-rows, NB/2 each).
// Stage: A tile 64x64h (8KB) at +0, B tile NBx64h at +8KB. Stage stride = 8KB + NB*128.
// Row = 128B; 16B chunk cq stored at cq ^ (row&7).
// DUAL=0: C[M,NB] fp16.  DUAL=1 (NB=128): C[M,64] fp16 = silu(G)*U*w; B rows interleave gate/up.
template<int DUAL, int NB>
__device__ __forceinline__ void gemm_body(
    const __half* __restrict__ A, const int* __restrict__ tokmap,
    const __half* __restrict__ Bg, const __half* __restrict__ Bu,
    __half* __restrict__ Cout, int ldo, const float* __restrict__ wrow,
    int K, int m0, int nb, int rowlim)
{
    constexpr int NJ   = NB / 32;              // B fragments (16 rows) per warp
    constexpr int NBCH = NB / 16;              // B cp16 chunks per thread per stage
    constexpr uint32_t STG = 8192 + NB * 128;

    extern __shared__ __half dsm[];
    uint32_t sbase = smem_u32(dsm);
    int tid = threadIdx.x, warp = tid >> 5, lane = tid & 31;
    int wm = warp & 1, wn = warp >> 1;
    int g = lane >> 2, t4 = lane & 3;
    int lrow = lane & 15, hi = lane >> 4;

    float c[2][2*NJ][4] = {};

    // ---- cp.async loaders: A 512 chunks (4/thr), B NB*8 chunks (NBCH/thr) ----
    const __half* aptr[4]; uint32_t adst[4];
    const __half* bptr[NBCH]; uint32_t bdst[NBCH];
    #pragma unroll
    for (int i = 0; i < 4; i++) {
        int id = i*128 + tid;
        int r = id >> 3, cq = id & 7;          // row 0..63
        int gr = m0 + r;
        int srow;
        if (tokmap) srow = (gr < rowlim) ? tokmap[gr] : 0;
        else        srow = gr;                 // buffers padded so OOB rows readable
        aptr[i] = A + (size_t)srow * K + cq*8;
        adst[i] = (uint32_t)(r*128 + ((cq ^ (r & 7)) << 4));
    }
    #pragma unroll
    for (int i = 0; i < NBCH; i++) {
        int id = i*128 + tid;
        int r = id >> 3, cq = id & 7;          // row 0..NB-1
        const __half* brow;
        if (DUAL) {
            int h = r >> 6, s = r & 63;
            brow = (s < 32) ? (Bg + (size_t)(nb + h*32 + s) * K)
                            : (Bu + (size_t)(nb + h*32 + s - 32) * K);
        } else {
            brow = Bg + (size_t)(nb + r) * K;
        }
        bptr[i] = brow + cq*8;
        bdst[i] = (uint32_t)(r*128 + ((cq ^ (r & 7)) << 4));
    }

    // ---- ldmatrix address components ----
    int arow0 = wm*32 + lrow, arow1 = arow0 + 16;
    uint32_t abase0 = arow0*128, abase1 = arow1*128;
    uint32_t arx0 = (uint32_t)(arow0 & 7) << 4, arx1 = (uint32_t)(arow1 & 7) << 4;
    uint32_t bbase[NJ], brx[NJ];
    #pragma unroll
    for (int j = 0; j < NJ; j++) {
        int br = wn*(NB/2) + j*16 + lrow;
        bbase[j] = br*128;
        brx[j] = (uint32_t)(br & 7) << 4;
    }

    int NK = K / 64;
    // ---- prologue: stage 0 ----
    {
        uint32_t sA = sbase, sB = sA + 8192;
        #pragma unroll
        for (int i = 0; i < 4; i++)    cp16(sA + adst[i], aptr[i]);
        #pragma unroll
        for (int i = 0; i < NBCH; i++) cp16(sB + bdst[i], bptr[i]);
        CP_COMMIT();
    }

    for (int kt = 0; kt < NK; kt++) {
        if (kt + 1 < NK) {
            uint32_t sA = sbase + ((kt+1) & 1)*STG, sB = sA + 8192;
            int ko = (kt + 1) * 64;
            #pragma unroll
            for (int i = 0; i < 4; i++)    cp16(sA + adst[i], aptr[i] + ko);
            #pragma unroll
            for (int i = 0; i < NBCH; i++) cp16(sB + bdst[i], bptr[i] + ko);
            CP_COMMIT();
            CP_WAIT1();
        } else {
            CP_WAIT0();
        }
        __syncthreads();
        uint32_t sA = sbase + (kt & 1)*STG, sB = sA + 8192;
        #pragma unroll
        for (int kk = 0; kk < 4; kk++) {
            uint32_t koff = (uint32_t)((kk*2 + hi) << 4);
            uint32_t a0[4], a1[4];
            ldsm_x4(a0[0], a0[1], a0[2], a0[3], sA + abase0 + (koff ^ arx0));
            ldsm_x4(a1[0], a1[1], a1[2], a1[3], sA + abase1 + (koff ^ arx1));
            #pragma unroll
            for (int j = 0; j < NJ; j++) {
                uint32_t r0, r1, r2, r3;
                ldsm_x4(r0, r1, r2, r3, sB + bbase[j] + (koff ^ brx[j]));
                mma16816(c[0][2*j],   a0, r0, r2);
                mma16816(c[0][2*j+1], a0, r1, r3);
                mma16816(c[1][2*j],   a1, r0, r2);
                mma16816(c[1][2*j+1], a1, r1, r3);
            }
        }
        __syncthreads();   // all warps done with buf kt&1 before next iteration overwrites it
    }

    // ---- epilogue (fp16 outputs in both modes) ----
    #pragma unroll
    for (int im = 0; im < 2; im++) {
        int rowa = m0 + wm*32 + im*16 + g;
        int rowb = rowa + 8;
        if (DUAL) {
            float wa = 1.f, wb = 1.f;
            if (wrow) {
                if (rowa < rowlim) wa = wrow[rowa];
                if (rowb < rowlim) wb = wrow[rowb];
            }
            #pragma unroll
            for (int in = 0; in < 4; in++) {
                int col = nb + wn*32 + in*8 + t4*2;
                if (rowa < rowlim) {
                    float v0 = siluf(c[im][in][0]) * c[im][in+4][0] * wa;
                    float v1 = siluf(c[im][in][1]) * c[im][in+4][1] * wa;
                    *(__half2*)&Cout[(size_t)rowa*ldo + col] = __floats2half2_rn(v0, v1);
                }
                if (rowb < rowlim) {
                    float v0 = siluf(c[im][in][2]) * c[im][in+4][2] * wb;
                    float v1 = siluf(c[im][in][3]) * c[im][in+4][3] * wb;
                    *(__half2*)&Cout[(size_t)rowb*ldo + col] = __floats2half2_rn(v0, v1);
                }
            }
        } else {
            #pragma unroll
            for (int in = 0; in < 2*NJ; in++) {
                int col = nb + wn*(NB/2) + in*8 + t4*2;
                if (rowa < rowlim)
                    *(__half2*)&Cout[(size_t)rowa*ldo + col] = __floats2half2_rn(c[im][in][0], c[im][in][1]);
                if (rowb < rowlim)
                    *(__half2*)&Cout[(size_t)rowb*ldo + col] = __floats2half2_rn(c[im][in][2], c[im][in][3]);
            }
        }
    }
}

#define SMEM_128 (2*(8192 + 128*128))   // 49152
#define SMEM_64  (2*(8192 + 64*128))    // 32768

// =============== GEMM wrappers ===============
__global__ __launch_bounds__(128, 4) void gemm_s1_k() {
    gemm_body<1,128>(g_xh, nullptr, g_sgw, g_suw, g_s1h, SIH, nullptr,
                     H, blockIdx.y*64, blockIdx.x*64, T);
}
__global__ __launch_bounds__(128, 4) void gemm_s2_k() {
    gemm_body<0,64>(g_s1h, nullptr, g_sdw, nullptr, g_shared2, H, nullptr,
                    SIH, blockIdx.y*64, blockIdx.x*64, T);
}
__global__ __launch_bounds__(128, 4) void gemm_e1_k() {
    int e = blockIdx.z;
    int cnt = g_count[e], base = g_offset[e];
    int m0 = blockIdx.y * 64;
    if (m0 >= cnt) return;
    const __half* W = g_gupw + (size_t)e * 2 * NI * H;
    gemm_body<1,128>(g_xh, g_pair_token + base, W, W + (size_t)NI * H,
                     g_acth + (size_t)base * NI, NI, g_pair_w + base,
                     H, m0, blockIdx.x*64, cnt);
}
__global__ __launch_bounds__(128, 4) void gemm_e2_k() {
    int e = blockIdx.z;
    int cnt = g_count[e], base = g_offset[e];
    int m0 = blockIdx.y * 64;
    if (m0 >= cnt) return;
    gemm_body<0,128>(g_acth + (size_t)base * NI, nullptr, g_dnw + (size_t)e * H * NI, nullptr,
                     g_pairout + (size_t)base * H, H, nullptr,
                     NI, m0, blockIdx.x*128, cnt);
}

// =============== routing ===============
__global__ void reset8_kernel() { if (threadIdx.x < E) g_count[threadIdx.x] = 0; }

__global__ void router_kernel(const float* __restrict__ x,
                              const float* __restrict__ rw,
                              const float* __restrict__ seg) {
    int warp = (blockIdx.x * blockDim.x + threadIdx.x) >> 5;
    int lane = threadIdx.x & 31;
    if (warp >= T) return;
    const float* xr = x + (size_t)warp * H;
    float acc[E];
    #pragma unroll
    for (int e = 0; e < E; e++) acc[e] = 0.f;
    float accg = 0.f;
    for (int k = lane; k < H; k += 32) {
        float xv = xr[k];
        #pragma unroll
        for (int e = 0; e < E; e++) acc[e] += xv * rw[e*H + k];
        accg += xv * seg[k];
    }
    #pragma unroll
    for (int o = 16; o > 0; o >>= 1) {
        #pragma unroll
        for (int e = 0; e < E; e++) acc[e] += __shfl_xor_sync(0xffffffffu, acc[e], o);
        accg += __shfl_xor_sync(0xffffffffu, accg, o);
    }
    if (lane == 0) {
        int be = 0; float bv = acc[0];
        #pragma unroll
        for (int e = 1; e < E; e++) if (acc[e] > bv) { bv = acc[e]; be = e; }
        int se = -1; float sv = -1e30f;
        #pragma unroll
        for (int e = 0; e < E; e++) if (e != be && acc[e] > sv) { sv = acc[e]; se = e; }
        float w0 = 1.f / (1.f + expf(sv - bv));
        float w1 = 1.f - w0;
        g_top_e[warp*2+0] = be; g_top_e[warp*2+1] = se;
        g_top_w[warp*2+0] = w0; g_top_w[warp*2+1] = w1;
        g_gl[warp] = accg;
        atomicAdd(&g_count[be], 1);
        atomicAdd(&g_count[se], 1);
    }
}

__global__ void scan_scatter_kernel() {
    __shared__ int s_fill[E];
    int tid = threadIdx.x;
    if (tid == 0) {
        int off = 0;
        for (int e = 0; e < E; e++) {
            g_offset[e] = off;
            s_fill[e] = off;
            off += g_count[e];
        }
    }
    __syncthreads();
    for (int t = tid; t < T; t += blockDim.x) {
        #pragma unroll
        for (int k = 0; k < 2; k++) {
            int e = g_top_e[t*2+k];
            int slot = atomicAdd(&s_fill[e], 1);
            g_pair_token[slot] = t;
            g_pair_w[slot] = g_top_w[t*2+k];
            g_pos[t*2+k] = slot;
        }
    }
}

// =============== fp32->fp16 conversion, split early/late ===============
__device__ __forceinline__ void cvt8(const float* __restrict__ src, __half* __restrict__ dst, size_t i) {
    float4 a = *(const float4*)(src + i);
    float4 b = *(const float4*)(src + i + 4);
    __half h[8];
    h[0]=__float2half_rn(a.x); h[1]=__float2half_rn(a.y); h[2]=__float2half_rn(a.z); h[3]=__float2half_rn(a.w);
    h[4]=__float2half_rn(b.x); h[5]=__float2half_rn(b.y); h[6]=__float2half_rn(b.z); h[7]=__float2half_rn(b.w);
    *(uint4*)(dst + i) = *(uint4*)h;
}
#define SZ_X   ((size_t)T*H)
#define SZ_SGW ((size_t)SIH*H)
#define SZ_SUW ((size_t)SIH*H)
#define SZ_SDW ((size_t)H*SIH)
#define SZ_GUP ((size_t)E*2*NI*H)
#define SZ_DN  ((size_t)E*H*NI)
#define E0 (SZ_X)
#define E1 (E0+SZ_SGW)
#define E2 (E1+SZ_SUW)
#define E3 (E2+SZ_GUP)
#define L0 (SZ_SDW)
#define L1 (L0+SZ_DN)
__device__ __forceinline__ void cvt8_early(size_t i,
    const float* x, const float* sgw, const float* suw, const float* gup) {
    if      (i < E0) cvt8(x,   g_xh,   i);
    else if (i < E1) cvt8(sgw, g_sgw,  i - E0);
    else if (i < E2) cvt8(suw, g_suw,  i - E1);
    else if (i < E3) cvt8(gup, g_gupw, i - E2);
}
__global__ void cvt_early_k(const float* __restrict__ x,   const float* __restrict__ sgw,
                            const float* __restrict__ suw, const float* __restrict__ gup) {
    size_t i = ((size_t)blockIdx.x * blockDim.x + threadIdx.x) * 16;
    cvt8_early(i, x, sgw, suw, gup);
    cvt8_early(i + 8, x, sgw, suw, gup);
}
__device__ __forceinline__ void cvt8_late(size_t i, const float* sdw, const float* dn) {
    if      (i < L0) cvt8(sdw, g_sdw, i);
    else if (i < L1) cvt8(dn,  g_dnw, i - L0);
}
__global__ void cvt_late_k(const float* __restrict__ sdw, const float* __restrict__ dn) {
    size_t i = ((size_t)blockIdx.x * blockDim.x + threadIdx.x) * 16;
    cvt8_late(i, sdw, dn);
    cvt8_late(i + 8, sdw, dn);
}

// =============== combine ===============
__global__ void combine_kernel(float* __restrict__ out) {
    int idx = blockIdx.x * blockDim.x + threadIdx.x;
    if (idx >= T*H/4) return;
    int t  = idx / (H/4);
    int c4 = (idx % (H/4)) * 4;
    int p0 = g_pos[t*2+0], p1 = g_pos[t*2+1];
    float sgate = 1.f / (1.f + expf(-g_gl[t]));
    __half2 a0 = *(__half2*)&g_pairout[(size_t)p0*H + c4];
    __half2 a1 = *(__half2*)&g_pairout[(size_t)p0*H + c4 + 2];
    __half2 b0 = *(__half2*)&g_pairout[(size_t)p1*H + c4];
    __half2 b1 = *(__half2*)&g_pairout[(size_t)p1*H + c4 + 2];
    __half2 s0 = *(__half2*)&g_shared2[(size_t)t*H + c4];
    __half2 s1 = *(__half2*)&g_shared2[(size_t)t*H + c4 + 2];
    float2 af0 = __half22float2(a0), af1 = __half22float2(a1);
    float2 bf0 = __half22float2(b0), bf1 = __half22float2(b1);
    float2 sf0 = __half22float2(s0), sf1 = __half22float2(s1);
    float4 o;
    o.x = af0.x + bf0.x + sgate * sf0.x;
    o.y = af0.y + bf0.y + sgate * sf0.y;
    o.z = af1.x + bf1.x + sgate * sf1.x;
    o.w = af1.y + bf1.y + sgate * sf1.y;
    *(float4*)&out[(size_t)t*H + c4] = o;
}

extern "C" void kernel_launch(void* const* d_in, const int* in_sizes, int n_in,
                              void* d_out, int out_size) {
    const float* x    = (const float*)d_in[0];
    const float* rw   = (const float*)d_in[1];
    const float* gup  = (const float*)d_in[2];
    const float* down = (const float*)d_in[3];
    const float* sgw  = (const float*)d_in[4];
    const float* suw  = (const float*)d_in[5];
    const float* sdw  = (const float*)d_in[6];
    const float* seg  = (const float*)d_in[7];
    float* out = (float*)d_out;

    static cudaStream_t st1 = nullptr, st2 = nullptr, st3 = nullptr;
    static cudaEvent_t ev0 = nullptr, evA = nullptr, evR = nullptr, evB = nullptr, evL = nullptr;
    static bool init_done = false;
    if (!init_done) {
        cudaFuncSetAttribute(gemm_s1_k, cudaFuncAttributeMaxDynamicSharedMemorySize, SMEM_128);
        cudaFuncSetAttribute(gemm_s2_k, cudaFuncAttributeMaxDynamicSharedMemorySize, SMEM_64);
        cudaFuncSetAttribute(gemm_e1_k, cudaFuncAttributeMaxDynamicSharedMemorySize, SMEM_128);
        cudaFuncSetAttribute(gemm_e2_k, cudaFuncAttributeMaxDynamicSharedMemorySize, SMEM_128);
        cudaStreamCreateWithFlags(&st1, cudaStreamNonBlocking);
        cudaStreamCreateWithFlags(&st2, cudaStreamNonBlocking);
        cudaStreamCreateWithFlags(&st3, cudaStreamNonBlocking);
        cudaEventCreateWithFlags(&ev0, cudaEventDisableTiming);
        cudaEventCreateWithFlags(&evA, cudaEventDisableTiming);
        cudaEventCreateWithFlags(&evR, cudaEventDisableTiming);
        cudaEventCreateWithFlags(&evB, cudaEventDisableTiming);
        cudaEventCreateWithFlags(&evL, cudaEventDisableTiming);
        init_done = true;
    }

    // fork
    cudaEventRecord(ev0, 0);
    cudaStreamWaitEvent(st1, ev0, 0);
    cudaStreamWaitEvent(st2, ev0, 0);
    cudaStreamWaitEvent(st3, ev0, 0);

    // st1: routing chain (overlaps cvt_early)
    reset8_kernel<<<1, 32, 0, st1>>>();
    router_kernel<<<T/8, 256, 0, st1>>>(x, rw, seg);
    scan_scatter_kernel<<<1, 1024, 0, st1>>>();
    cudaEventRecord(evR, st1);

    // main: phase-1 operand conversion
    cvt_early_k<<<(unsigned)((E3/16 + 255)/256), 256>>>(x, sgw, suw, gup);
    cudaEventRecord(evA, 0);

    // st3: phase-2 operand conversion overlapped with phase-1 GEMMs
    cudaStreamWaitEvent(st3, evA, 0);
    cvt_late_k<<<(unsigned)((L1/16 + 255)/256), 256, 0, st3>>>(sdw, down);
    cudaEventRecord(evL, st3);

    // st2: shared-expert chain
    cudaStreamWaitEvent(st2, evA, 0);
    gemm_s1_k<<<dim3(SIH/64, T/64), 128, SMEM_128, st2>>>();
    cudaStreamWaitEvent(st2, evL, 0);
    gemm_s2_k<<<dim3(H/64, T/64), 128, SMEM_64, st2>>>();
    cudaEventRecord(evB, st2);

    // main: expert chain
    cudaStreamWaitEvent(0, evR, 0);
    gemm_e1_k<<<dim3(NI/64, NPAIR/64, E), 128, SMEM_128>>>();
    cudaStreamWaitEvent(0, evL, 0);
    gemm_e2_k<<<dim3(H/128, NPAIR/64, E), 128, SMEM_128>>>();

    // join
    cudaStreamWaitEvent(0, evB, 0);
    combine_kernel<<<(T*H/4 + 255)/256, 256>>>(out);
}

// round 15
// speedup vs baseline: 1.0547x; 1.0004x over previous
#include <cuda_runtime.h>
#include <cuda_fp16.h>
#include <cstdint>
#include <math.h>

#define T 2048
#define H 1024
#define E 8
#define NI 512          // I
#define SIH 2048        // SI
#define NPAIR (2*T)

// ---- fp16 operand buffers ----
__device__ __half g_xh [(size_t)T*H];
__device__ __half g_sgw[(size_t)SIH*H];
__device__ __half g_suw[(size_t)SIH*H];
__device__ __half g_sdw[(size_t)H*SIH];
__device__ __half g_gupw[(size_t)E*2*NI*H];
__device__ __half g_dnw[(size_t)E*H*NI];
__device__ __half g_s1h[(size_t)T*SIH];            // shared SwiGLU intermediate (fp16)
__device__ __half g_acth[(size_t)(NPAIR+128)*NI];  // expert SwiGLU intermediate (+pad rows)
// ---- fp16 GEMM outputs ----
__device__ __half g_shared2[(size_t)T*H];
__device__ __half g_pairout[(size_t)NPAIR*H];
// ---- routing state ----
__device__ int   g_top_e[T*2];
__device__ float g_top_w[T*2];
__device__ float g_gl[T];
__device__ int   g_count[E];
__device__ int   g_pair_token[NPAIR];
__device__ float g_pair_w[NPAIR];
__device__ int   g_pos[T*2];
__device__ int   g_offset[E];

// =============== PTX helpers ===============
__device__ __forceinline__ uint32_t smem_u32(const void* p) {
    uint32_t a;
    asm("{ .reg .u64 t; cvta.to.shared.u64 t, %1; cvt.u32.u64 %0, t; }" : "=r"(a) : "l"(p));
    return a;
}
__device__ __forceinline__ void cp16(uint32_t dst, const void* src) {
    asm volatile("cp.async.cg.shared.global [%0], [%1], 16;" :: "r"(dst), "l"(src) : "memory");
}
#define CP_COMMIT() asm volatile("cp.async.commit_group;" ::: "memory")
#define CP_WAIT1()  asm volatile("cp.async.wait_group 1;" ::: "memory")
#define CP_WAIT0()  asm volatile("cp.async.wait_group 0;" ::: "memory")

__device__ __forceinline__ void ldsm_x4(uint32_t& r0, uint32_t& r1, uint32_t& r2, uint32_t& r3, uint32_t addr) {
    asm volatile("ldmatrix.sync.aligned.m8n8.x4.shared.b16 {%0,%1,%2,%3}, [%4];"
        : "=r"(r0), "=r"(r1), "=r"(r2), "=r"(r3) : "r"(addr));
}
__device__ __forceinline__ void mma16816(float* c, const uint32_t* a, uint32_t b0, uint32_t b1) {
    asm("mma.sync.aligned.m16n8k16.row.col.f32.f16.f16.f32 "
        "{%0,%1,%2,%3}, {%4,%5,%6,%7}, {%8,%9}, {%0,%1,%2,%3};\n"
        : "+f"(c[0]), "+f"(c[1]), "+f"(c[2]), "+f"(c[3])
        : "r"(a[0]), "r"(a[1]), "r"(a[2]), "r"(a[3]), "r"(b0), "r"(b1));
}

__device__ __forceinline__ float siluf(float g) { return g / (1.f + expf(-g)); }

// =============== GEMM core: 64(M) x NB(B-rows) x K, k-chunk 64, 2-stage cp.async, 128 threads ===============
template<int DUAL, int NB>
__device__ __forceinline__ void gemm_body(
    const __half* __restrict__ A, const int* __restrict__ tokmap,
    const __half* __restrict__ Bg, const __half* __restrict__ Bu,
    __half* __restrict__ Cout, int ldo, const float* __restrict__ wrow,
    int K, int m0, int nb, int rowlim)
{
    constexpr int NJ   = NB / 32;
    constexpr int NBCH = NB / 16;
    constexpr uint32_t STG = 8192 + NB * 128;

    extern __shared__ __half dsm[];
    uint32_t sbase = smem_u32(dsm);
    int tid = threadIdx.x, warp = tid >> 5, lane = tid & 31;
    int wm = warp & 1, wn = warp >> 1;
    int g = lane >> 2, t4 = lane & 3;
    int lrow = lane & 15, hi = lane >> 4;

    float c[2][2*NJ][4] = {};

    const __half* aptr[4]; uint32_t adst[4];
    const __half* bptr[NBCH]; uint32_t bdst[NBCH];
    #pragma unroll
    for (int i = 0; i < 4; i++) {
        int id = i*128 + tid;
        int r = id >> 3, cq = id & 7;
        int gr = m0 + r;
        int srow;
        if (tokmap) srow = (gr < rowlim) ? tokmap[gr] : 0;
        else        srow = gr;
        aptr[i] = A + (size_t)srow * K + cq*8;
        adst[i] = (uint32_t)(r*128 + ((cq ^ (r & 7)) << 4));
    }
    #pragma unroll
    for (int i = 0; i < NBCH; i++) {
        int id = i*128 + tid;
        int r = id >> 3, cq = id & 7;
        const __half* brow;
        if (DUAL) {
            int h = r >> 6, s = r & 63;
            brow = (s < 32) ? (Bg + (size_t)(nb + h*32 + s) * K)
                            : (Bu + (size_t)(nb + h*32 + s - 32) * K);
        } else {
            brow = Bg + (size_t)(nb + r) * K;
        }
        bptr[i] = brow + cq*8;
        bdst[i] = (uint32_t)(r*128 + ((cq ^ (r & 7)) << 4));
    }

    int arow0 = wm*32 + lrow, arow1 = arow0 + 16;
    uint32_t abase0 = arow0*128, abase1 = arow1*128;
    uint32_t arx0 = (uint32_t)(arow0 & 7) << 4, arx1 = (uint32_t)(arow1 & 7) << 4;
    uint32_t bbase[NJ], brx[NJ];
    #pragma unroll
    for (int j = 0; j < NJ; j++) {
        int br = wn*(NB/2) + j*16 + lrow;
        bbase[j] = br*128;
        brx[j] = (uint32_t)(br & 7) << 4;
    }

    int NK = K / 64;
    {
        uint32_t sA = sbase, sB = sA + 8192;
        #pragma unroll
        for (int i = 0; i < 4; i++)    cp16(sA + adst[i], aptr[i]);
        #pragma unroll
        for (int i = 0; i < NBCH; i++) cp16(sB + bdst[i], bptr[i]);
        CP_COMMIT();
    }

    for (int kt = 0; kt < NK; kt++) {
        if (kt + 1 < NK) {
            uint32_t sA = sbase + ((kt+1) & 1)*STG, sB = sA + 8192;
            int ko = (kt + 1) * 64;
            #pragma unroll
            for (int i = 0; i < 4; i++)    cp16(sA + adst[i], aptr[i] + ko);
            #pragma unroll
            for (int i = 0; i < NBCH; i++) cp16(sB + bdst[i], bptr[i] + ko);
            CP_COMMIT();
            CP_WAIT1();
        } else {
            CP_WAIT0();
        }
        __syncthreads();
        uint32_t sA = sbase + (kt & 1)*STG, sB = sA + 8192;
        #pragma unroll
        for (int kk = 0; kk < 4; kk++) {
            uint32_t koff = (uint32_t)((kk*2 + hi) << 4);
            uint32_t a0[4], a1[4];
            ldsm_x4(a0[0], a0[1], a0[2], a0[3], sA + abase0 + (koff ^ arx0));
            ldsm_x4(a1[0], a1[1], a1[2], a1[3], sA + abase1 + (koff ^ arx1));
            #pragma unroll
            for (int j = 0; j < NJ; j++) {
                uint32_t r0, r1, r2, r3;
                ldsm_x4(r0, r1, r2, r3, sB + bbase[j] + (koff ^ brx[j]));
                mma16816(c[0][2*j],   a0, r0, r2);
                mma16816(c[0][2*j+1], a0, r1, r3);
                mma16816(c[1][2*j],   a1, r0, r2);
                mma16816(c[1][2*j+1], a1, r1, r3);
            }
        }
        __syncthreads();
    }

    #pragma unroll
    for (int im = 0; im < 2; im++) {
        int rowa = m0 + wm*32 + im*16 + g;
        int rowb = rowa + 8;
        if (DUAL) {
            float wa = 1.f, wb = 1.f;
            if (wrow) {
                if (rowa < rowlim) wa = wrow[rowa];
                if (rowb < rowlim) wb = wrow[rowb];
            }
            #pragma unroll
            for (int in = 0; in < 4; in++) {
                int col = nb + wn*32 + in*8 + t4*2;
                if (rowa < rowlim) {
                    float v0 = siluf(c[im][in][0]) * c[im][in+4][0] * wa;
                    float v1 = siluf(c[im][in][1]) * c[im][in+4][1] * wa;
                    *(__half2*)&Cout[(size_t)rowa*ldo + col] = __floats2half2_rn(v0, v1);
                }
                if (rowb < rowlim) {
                    float v0 = siluf(c[im][in][2]) * c[im][in+4][2] * wb;
                    float v1 = siluf(c[im][in][3]) * c[im][in+4][3] * wb;
                    *(__half2*)&Cout[(size_t)rowb*ldo + col] = __floats2half2_rn(v0, v1);
                }
            }
        } else {
            #pragma unroll
            for (int in = 0; in < 2*NJ; in++) {
                int col = nb + wn*(NB/2) + in*8 + t4*2;
                if (rowa < rowlim)
                    *(__half2*)&Cout[(size_t)rowa*ldo + col] = __floats2half2_rn(c[im][in][0], c[im][in][1]);
                if (rowb < rowlim)
                    *(__half2*)&Cout[(size_t)rowb*ldo + col] = __floats2half2_rn(c[im][in][2], c[im][in][3]);
            }
        }
    }
}

#define SMEM_128 (2*(8192 + 128*128))   // 49152
#define SMEM_64  (2*(8192 + 64*128))    // 32768

// =============== GEMM wrappers ===============
__global__ __launch_bounds__(128, 4) void gemm_s1_k() {
    gemm_body<1,128>(g_xh, nullptr, g_sgw, g_suw, g_s1h, SIH, nullptr,
                     H, blockIdx.y*64, blockIdx.x*64, T);
}
__global__ __launch_bounds__(128, 4) void gemm_s2_k() {
    gemm_body<0,64>(g_s1h, nullptr, g_sdw, nullptr, g_shared2, H, nullptr,
                    SIH, blockIdx.y*64, blockIdx.x*64, T);
}
__global__ __launch_bounds__(128, 4) void gemm_e1_k() {
    int e = blockIdx.z;
    int cnt = g_count[e], base = g_offset[e];
    int m0 = blockIdx.y * 64;
    if (m0 >= cnt) return;
    const __half* W = g_gupw + (size_t)e * 2 * NI * H;
    gemm_body<1,128>(g_xh, g_pair_token + base, W, W + (size_t)NI * H,
                     g_acth + (size_t)base * NI, NI, g_pair_w + base,
                     H, m0, blockIdx.x*64, cnt);
}
__global__ __launch_bounds__(128, 4) void gemm_e2_k() {
    int e = blockIdx.z;
    int cnt = g_count[e], base = g_offset[e];
    int m0 = blockIdx.y * 64;
    if (m0 >= cnt) return;
    gemm_body<0,128>(g_acth + (size_t)base * NI, nullptr, g_dnw + (size_t)e * H * NI, nullptr,
                     g_pairout + (size_t)base * H, H, nullptr,
                     NI, m0, blockIdx.x*128, cnt);
}

// =============== routing ===============
__global__ void reset8_kernel() { if (threadIdx.x < E) g_count[threadIdx.x] = 0; }

__global__ void router_kernel(const float* __restrict__ x,
                              const float* __restrict__ rw,
                              const float* __restrict__ seg) {
    int warp = (blockIdx.x * blockDim.x + threadIdx.x) >> 5;
    int lane = threadIdx.x & 31;
    if (warp >= T) return;
    const float* xr = x + (size_t)warp * H;
    float acc[E];
    #pragma unroll
    for (int e = 0; e < E; e++) acc[e] = 0.f;
    float accg = 0.f;
    for (int k = lane; k < H; k += 32) {
        float xv = xr[k];
        #pragma unroll
        for (int e = 0; e < E; e++) acc[e] += xv * rw[e*H + k];
        accg += xv * seg[k];
    }
    #pragma unroll
    for (int o = 16; o > 0; o >>= 1) {
        #pragma unroll
        for (int e = 0; e < E; e++) acc[e] += __shfl_xor_sync(0xffffffffu, acc[e], o);
        accg += __shfl_xor_sync(0xffffffffu, accg, o);
    }
    if (lane == 0) {
        int be = 0; float bv = acc[0];
        #pragma unroll
        for (int e = 1; e < E; e++) if (acc[e] > bv) { bv = acc[e]; be = e; }
        int se = -1; float sv = -1e30f;
        #pragma unroll
        for (int e = 0; e < E; e++) if (e != be && acc[e] > sv) { sv = acc[e]; se = e; }
        float w0 = 1.f / (1.f + expf(sv - bv));
        float w1 = 1.f - w0;
        g_top_e[warp*2+0] = be; g_top_e[warp*2+1] = se;
        g_top_w[warp*2+0] = w0; g_top_w[warp*2+1] = w1;
        g_gl[warp] = accg;
        atomicAdd(&g_count[be], 1);
        atomicAdd(&g_count[se], 1);
    }
}

__global__ void scan_scatter_kernel() {
    __shared__ int s_fill[E];
    int tid = threadIdx.x;
    if (tid == 0) {
        int off = 0;
        for (int e = 0; e < E; e++) {
            g_offset[e] = off;
            s_fill[e] = off;
            off += g_count[e];
        }
    }
    __syncthreads();
    for (int t = tid; t < T; t += blockDim.x) {
        #pragma unroll
        for (int k = 0; k < 2; k++) {
            int e = g_top_e[t*2+k];
            int slot = atomicAdd(&s_fill[e], 1);
            g_pair_token[slot] = t;
            g_pair_w[slot] = g_top_w[t*2+k];
            g_pos[t*2+k] = slot;
        }
    }
}

// =============== fp32->fp16 conversion, three kernels / 3-stream topology ===============
__device__ __forceinline__ void cvt8(const float* __restrict__ src, __half* __restrict__ dst, size_t i) {
    float4 a = *(const float4*)(src + i);
    float4 b = *(const float4*)(src + i + 4);
    __half h[8];
    h[0]=__float2half_rn(a.x); h[1]=__float2half_rn(a.y); h[2]=__float2half_rn(a.z); h[3]=__float2half_rn(a.w);
    h[4]=__float2half_rn(b.x); h[5]=__float2half_rn(b.y); h[6]=__float2half_rn(b.z); h[7]=__float2half_rn(b.w);
    *(uint4*)(dst + i) = *(uint4*)h;
}
#define SZ_X   ((size_t)T*H)
#define SZ_SGW ((size_t)SIH*H)
#define SZ_SUW ((size_t)SIH*H)
#define SZ_SDW ((size_t)H*SIH)
#define SZ_GUP ((size_t)E*2*NI*H)
#define SZ_DN  ((size_t)E*H*NI)
// critical: x, sgw, suw (s1 operands)
#define K0 (SZ_X)
#define K1 (K0+SZ_SGW)
#define K2 (K1+SZ_SUW)
// late: sdw, dn
#define L0 (SZ_SDW)
#define L1 (L0+SZ_DN)
__device__ __forceinline__ void cvt8_crit(size_t i,
    const float* x, const float* sgw, const float* suw) {
    if      (i < K0) cvt8(x,   g_xh,  i);
    else if (i < K1) cvt8(sgw, g_sgw, i - K0);
    else if (i < K2) cvt8(suw, g_suw, i - K1);
}
__global__ void cvt_crit_k(const float* __restrict__ x, const float* __restrict__ sgw,
                           const float* __restrict__ suw) {
    size_t i = ((size_t)blockIdx.x * blockDim.x + threadIdx.x) * 16;
    cvt8_crit(i, x, sgw, suw);
    cvt8_crit(i + 8, x, sgw, suw);
}
__global__ void cvt_g_k(const float* __restrict__ gup) {
    size_t i = ((size_t)blockIdx.x * blockDim.x + threadIdx.x) * 16;
    if (i < SZ_GUP)     cvt8(gup, g_gupw, i);
    if (i + 8 < SZ_GUP) cvt8(gup, g_gupw, i + 8);
}
__device__ __forceinline__ void cvt8_late(size_t i, const float* sdw, const float* dn) {
    if      (i < L0) cvt8(sdw, g_sdw, i);
    else if (i < L1) cvt8(dn,  g_dnw, i - L0);
}
__global__ void cvt_late_k(const float* __restrict__ sdw, const float* __restrict__ dn) {
    size_t i = ((size_t)blockIdx.x * blockDim.x + threadIdx.x) * 16;
    cvt8_late(i, sdw, dn);
    cvt8_late(i + 8, sdw, dn);
}

// =============== combine ===============
__global__ void combine_kernel(float* __restrict__ out) {
    int idx = blockIdx.x * blockDim.x + threadIdx.x;
    if (idx >= T*H/4) return;
    int t  = idx / (H/4);
    int c4 = (idx % (H/4)) * 4;
    int p0 = g_pos[t*2+0], p1 = g_pos[t*2+1];
    float sgate = 1.f / (1.f + expf(-g_gl[t]));
    __half2 a0 = *(__half2*)&g_pairout[(size_t)p0*H + c4];
    __half2 a1 = *(__half2*)&g_pairout[(size_t)p0*H + c4 + 2];
    __half2 b0 = *(__half2*)&g_pairout[(size_t)p1*H + c4];
    __half2 b1 = *(__half2*)&g_pairout[(size_t)p1*H + c4 + 2];
    __half2 s0 = *(__half2*)&g_shared2[(size_t)t*H + c4];
    __half2 s1 = *(__half2*)&g_shared2[(size_t)t*H + c4 + 2];
    float2 af0 = __half22float2(a0), af1 = __half22float2(a1);
    float2 bf0 = __half22float2(b0), bf1 = __half22float2(b1);
    float2 sf0 = __half22float2(s0), sf1 = __half22float2(s1);
    float4 o;
    o.x = af0.x + bf0.x + sgate * sf0.x;
    o.y = af0.y + bf0.y + sgate * sf0.y;
    o.z = af1.x + bf1.x + sgate * sf1.x;
    o.w = af1.y + bf1.y + sgate * sf1.y;
    *(float4*)&out[(size_t)t*H + c4] = o;
}

extern "C" void kernel_launch(void* const* d_in, const int* in_sizes, int n_in,
                              void* d_out, int out_size) {
    const float* x    = (const float*)d_in[0];
    const float* rw   = (const float*)d_in[1];
    const float* gup  = (const float*)d_in[2];
    const float* down = (const float*)d_in[3];
    const float* sgw  = (const float*)d_in[4];
    const float* suw  = (const float*)d_in[5];
    const float* sdw  = (const float*)d_in[6];
    const float* seg  = (const float*)d_in[7];
    float* out = (float*)d_out;

    static cudaStream_t st1 = nullptr, st2 = nullptr, st3 = nullptr;
    static cudaEvent_t ev0 = nullptr, evA = nullptr, evR = nullptr, evB = nullptr, evL = nullptr;
    static bool init_done = false;
    if (!init_done) {
        cudaFuncSetAttribute(gemm_s1_k, cudaFuncAttributeMaxDynamicSharedMemorySize, SMEM_128);
        cudaFuncSetAttribute(gemm_s2_k, cudaFuncAttributeMaxDynamicSharedMemorySize, SMEM_64);
        cudaFuncSetAttribute(gemm_e1_k, cudaFuncAttributeMaxDynamicSharedMemorySize, SMEM_128);
        cudaFuncSetAttribute(gemm_e2_k, cudaFuncAttributeMaxDynamicSharedMemorySize, SMEM_128);
        cudaStreamCreateWithFlags(&st1, cudaStreamNonBlocking);
        cudaStreamCreateWithFlags(&st2, cudaStreamNonBlocking);
        cudaStreamCreateWithFlags(&st3, cudaStreamNonBlocking);
        cudaEventCreateWithFlags(&ev0, cudaEventDisableTiming);
        cudaEventCreateWithFlags(&evA, cudaEventDisableTiming);
        cudaEventCreateWithFlags(&evR, cudaEventDisableTiming);
        cudaEventCreateWithFlags(&evB, cudaEventDisableTiming);
        cudaEventCreateWithFlags(&evL, cudaEventDisableTiming);
        init_done = true;
    }

    // fork (same 3-stream / 5-event topology as the passing R13 run)
    cudaEventRecord(ev0, 0);
    cudaStreamWaitEvent(st1, ev0, 0);
    cudaStreamWaitEvent(st2, ev0, 0);
    cudaStreamWaitEvent(st3, ev0, 0);

    // st1: routing chain (overlaps cvt_crit)
    reset8_kernel<<<1, 32, 0, st1>>>();
    router_kernel<<<T/8, 256, 0, st1>>>(x, rw, seg);
    scan_scatter_kernel<<<1, 1024, 0, st1>>>();
    cudaEventRecord(evR, st1);

    // main: s1-operand conversion only (x, sgw, suw) — short critical prefix
    cvt_crit_k<<<(unsigned)((K2/16 + 255)/256), 256>>>(x, sgw, suw);
    cudaEventRecord(evA, 0);

    // main (stream-ordered, no extra event): gup conversion before e1
    cvt_g_k<<<(unsigned)((SZ_GUP/16 + 255)/256), 256>>>(gup);

    // st3: phase-2 weight conversion (sdw, dn) — overlaps cvt_g / s1
    cudaStreamWaitEvent(st3, evA, 0);
    cvt_late_k<<<(unsigned)((L1/16 + 255)/256), 256, 0, st3>>>(sdw, down);
    cudaEventRecord(evL, st3);

    // st2: shared-expert chain — starts right after cvt_crit (~6.5us)
    cudaStreamWaitEvent(st2, evA, 0);
    gemm_s1_k<<<dim3(SIH/64, T/64), 128, SMEM_128, st2>>>();
    cudaStreamWaitEvent(st2, evL, 0);
    gemm_s2_k<<<dim3(H/64, T/64), 128, SMEM_64, st2>>>();
    cudaEventRecord(evB, st2);

    // main: expert chain (gup via stream order; routing via evR; dnw via evL)
    cudaStreamWaitEvent(0, evR, 0);
    gemm_e1_k<<<dim3(NI/64, NPAIR/64, E), 128, SMEM_128>>>();
    cudaStreamWaitEvent(0, evL, 0);
    gemm_e2_k<<<dim3(H/128, NPAIR/64, E), 128, SMEM_128>>>();

    // join
    cudaStreamWaitEvent(0, evB, 0);
    combine_kernel<<<(T*H/4 + 255)/256, 256>>>(out);
}